// round 4
// baseline (speedup 1.0000x reference)
#include <cuda_runtime.h>
#include <math.h>

#define NN 10000
#define EE 160000
#define HH 4
#define MPAD 10112   // 79 * 128

// ---------------- static scratch ----------------
__device__ float g_C   [NN * 1408];    // [N, NCATP] fused GEMM out (feat|res|el|er|pad)
__device__ float g_Bcat[128 * 1408];
__device__ float g_hA  [NN * 128];
__device__ float g_hB  [NN * 128];
__device__ float g_AT  [128 * MPAD];
__device__ float g_eedge[EE * HH];
__device__ int   g_off [NN + 1];
__device__ int   g_cur [NN];
__device__ int   g_csrc[EE];
__device__ int   g_ceid[EE];
__device__ float g_wev [64 * HH];

// ---------------- packed f32x2 FMA ----------------
__device__ __forceinline__ void ffma2(float2& c, float a, float2 b) {
    float2 a2 = make_float2(a, a);
    unsigned long long aa = *reinterpret_cast<unsigned long long*>(&a2);
    unsigned long long bb = *reinterpret_cast<unsigned long long*>(&b);
    unsigned long long cc = *reinterpret_cast<unsigned long long*>(&c);
    asm("fma.rn.f32x2 %0, %1, %2, %0;" : "+l"(cc) : "l"(aa), "l"(bb));
    c = *reinterpret_cast<float2*>(&cc);
}
__device__ __forceinline__ unsigned smem_u32(const void* p) {
    return (unsigned)__cvta_generic_to_shared(p);
}
__device__ __forceinline__ void cpa16(unsigned s, const float* g) {
    asm volatile("cp.async.cg.shared.global [%0], [%1], 16;" :: "r"(s), "l"(g));
}

// ---------------- transpose x[M,128] -> AT[128,MPAD] (layer 0 only) ---------
__global__ void transpose_kernel(const float* __restrict__ x, float* __restrict__ AT, int M) {
    __shared__ float t[32][33];
    int mBase = blockIdx.x * 32;
    int kBase = blockIdx.y * 32;
    int lx = threadIdx.x, ly = threadIdx.y;
#pragma unroll
    for (int j = 0; j < 32; j += 8) {
        int m = mBase + ly + j;
        t[ly + j][lx] = (m < M) ? x[(size_t)m * 128 + kBase + lx] : 0.f;
    }
    __syncthreads();
#pragma unroll
    for (int j = 0; j < 32; j += 8)
        AT[(size_t)(kBase + ly + j) * MPAD + mBase + lx] = t[lx][ly + j];
}

// ---------------- build Bcat = [W | res | (al ar via contract) | 0] ---------
__global__ void bcat_kernel(const float* __restrict__ W, const float* __restrict__ res,
                            float* __restrict__ Bcat, int D, int NCATP) {
    int t = blockIdx.x * blockDim.x + threadIdx.x;
    if (t >= 128 * NCATP) return;
    int i = t / NCATP, c = t - i * NCATP;
    if (c < 4 * D)            Bcat[t] = W[(size_t)i * 4 * D + c];
    else if (c < 5 * D)       Bcat[t] = res[(size_t)i * D + (c - 4 * D)];
    else if (c >= 5 * D + 8)  Bcat[t] = 0.f;
}

__global__ void contract_kernel(const float* __restrict__ W,
                                const float* __restrict__ vl, const float* __restrict__ vr,
                                float* __restrict__ Bcat, int D, int NCATP) {
    int t = blockIdx.x * blockDim.x + threadIdx.x;
    if (t >= 128 * HH) return;
    int i = t >> 2, h = t & 3;
    const float* wr = W + (size_t)(i * HH + h) * D;
    const float* al = vl + h * D;
    const float* ar = vr + h * D;
    float sl = 0.f, sr = 0.f;
    for (int d = 0; d < D; d++) {
        float w = wr[d];
        sl = fmaf(w, al[d], sl);
        sr = fmaf(w, ar[d], sr);
    }
    Bcat[(size_t)i * NCATP + 5 * D + h]     = sl;
    Bcat[(size_t)i * NCATP + 5 * D + 4 + h] = sr;
}

__global__ void contract_we(const float* __restrict__ We, const float* __restrict__ ae) {
    int t = blockIdx.x * blockDim.x + threadIdx.x;
    if (t >= 64 * HH) return;
    int i = t >> 2, h = t & 3;
    const float* wr = We + (size_t)(i * HH + h) * 128;
    const float* a  = ae + h * 128;
    float s = 0.f;
    for (int d = 0; d < 128; d++) s = fmaf(wr[d], a[d], s);
    g_wev[t] = s;
}

// ---------------- SGEMM: BM=128 BN=128 BK=16, 256 thr, 8x8 tile, f32x2 ------
__global__ void __launch_bounds__(256) sgemm_tc(const float* __restrict__ AT,
                                                const float* __restrict__ B,
                                                float* __restrict__ C, int M, int Nc) {
    __shared__ float As[2][16][128];
    __shared__ float Bs[2][16][128];
    int tid = threadIdx.x;
    int tx = tid & 15, ty = tid >> 4;
    int rowBase = blockIdx.x * 128;
    int colBase = blockIdx.y * 128;

    float2 acc[8][4];
#pragma unroll
    for (int i = 0; i < 8; i++)
#pragma unroll
        for (int j = 0; j < 4; j++) acc[i][j] = make_float2(0.f, 0.f);

    int ka = tid >> 5, ma = (tid & 31) * 4;   // two float4 each for A and B

    cpa16(smem_u32(&As[0][ka][ma]),     AT + (size_t)ka * MPAD + rowBase + ma);
    cpa16(smem_u32(&As[0][ka + 8][ma]), AT + (size_t)(ka + 8) * MPAD + rowBase + ma);
    cpa16(smem_u32(&Bs[0][ka][ma]),     B + (size_t)ka * Nc + colBase + ma);
    cpa16(smem_u32(&Bs[0][ka + 8][ma]), B + (size_t)(ka + 8) * Nc + colBase + ma);
    asm volatile("cp.async.commit_group;" ::: "memory");

    for (int kb = 0; kb < 8; kb++) {
        int cur = kb & 1;
        asm volatile("cp.async.wait_group 0;" ::: "memory");
        __syncthreads();
        if (kb < 7) {
            int k0 = (kb + 1) * 16;
            cpa16(smem_u32(&As[cur ^ 1][ka][ma]),     AT + (size_t)(k0 + ka) * MPAD + rowBase + ma);
            cpa16(smem_u32(&As[cur ^ 1][ka + 8][ma]), AT + (size_t)(k0 + ka + 8) * MPAD + rowBase + ma);
            cpa16(smem_u32(&Bs[cur ^ 1][ka][ma]),     B + (size_t)(k0 + ka) * Nc + colBase + ma);
            cpa16(smem_u32(&Bs[cur ^ 1][ka + 8][ma]), B + (size_t)(k0 + ka + 8) * Nc + colBase + ma);
            asm volatile("cp.async.commit_group;" ::: "memory");
        }
#pragma unroll
        for (int k = 0; k < 16; k++) {
            float4 a0 = *(const float4*)&As[cur][k][ty * 8];
            float4 a1 = *(const float4*)&As[cur][k][ty * 8 + 4];
            float4 bA = *(const float4*)&Bs[cur][k][tx * 8];
            float4 bB = *(const float4*)&Bs[cur][k][tx * 8 + 4];
            float2 b0 = make_float2(bA.x, bA.y);
            float2 b1 = make_float2(bA.z, bA.w);
            float2 b2 = make_float2(bB.x, bB.y);
            float2 b3 = make_float2(bB.z, bB.w);
            float av[8] = {a0.x, a0.y, a0.z, a0.w, a1.x, a1.y, a1.z, a1.w};
#pragma unroll
            for (int i = 0; i < 8; i++) {
                ffma2(acc[i][0], av[i], b0);
                ffma2(acc[i][1], av[i], b1);
                ffma2(acc[i][2], av[i], b2);
                ffma2(acc[i][3], av[i], b3);
            }
        }
    }
#pragma unroll
    for (int i = 0; i < 8; i++) {
        int row = rowBase + ty * 8 + i;
        if (row < M) {
            float4 o0 = make_float4(acc[i][0].x, acc[i][0].y, acc[i][1].x, acc[i][1].y);
            float4 o1 = make_float4(acc[i][2].x, acc[i][2].y, acc[i][3].x, acc[i][3].y);
            *(float4*)(C + (size_t)row * Nc + colBase + tx * 8)     = o0;
            *(float4*)(C + (size_t)row * Nc + colBase + tx * 8 + 4) = o1;
        }
    }
}

// ---------------- edge logit term (layer 1 only) ----------------
__global__ void __launch_bounds__(256) eedge_kernel(const float* __restrict__ ef) {
    __shared__ float sf[64][68];
    __shared__ float sw[64 * HH];
    int tid = threadIdx.x;
    int e0 = blockIdx.x * 64;
    sw[tid] = g_wev[tid];
#pragma unroll
    for (int j = 0; j < 4; j++) {
        int idx = tid + j * 256;
        int e = idx >> 4, q = idx & 15;
        float4 v = *(const float4*)(ef + (size_t)(e0 + e) * 64 + q * 4);
        *(float4*)&sf[e][q * 4] = v;
    }
    __syncthreads();
    int e = tid >> 2, h = tid & 3;
    float acc = 0.f;
#pragma unroll
    for (int d = 0; d < 64; d++)
        acc = fmaf(sf[e][d], sw[d * 4 + h], acc);
    g_eedge[(size_t)(e0 + e) * 4 + h] = acc;
}

// ---------------- CSR build ----------------
__global__ void zero_cur() {
    int i = blockIdx.x * blockDim.x + threadIdx.x;
    if (i < NN) g_cur[i] = 0;
}
__global__ void count_kernel(const int* __restrict__ dst) {
    int e = blockIdx.x * blockDim.x + threadIdx.x;
    if (e < EE) atomicAdd(&g_cur[dst[e]], 1);
}
__global__ void scan_kernel() {
    __shared__ int sh[1024];
    int t = threadIdx.x;
    int vals[10];
    int base = t * 10;
    int s = 0;
#pragma unroll
    for (int j = 0; j < 10; j++) {
        int idx = base + j;
        int v = (idx < NN) ? g_cur[idx] : 0;
        vals[j] = s;
        s += v;
    }
    sh[t] = s;
    __syncthreads();
    for (int off = 1; off < 1024; off <<= 1) {
        int v = (t >= off) ? sh[t - off] : 0;
        __syncthreads();
        sh[t] += v;
        __syncthreads();
    }
    int excl = (t > 0) ? sh[t - 1] : 0;
#pragma unroll
    for (int j = 0; j < 10; j++) {
        int idx = base + j;
        if (idx < NN) {
            int o = excl + vals[j];
            g_off[idx] = o;
            g_cur[idx] = o;
        }
    }
    if (t == 1023) g_off[NN] = sh[1023];
}
__global__ void scatter_kernel(const int* __restrict__ src, const int* __restrict__ dst) {
    int e = blockIdx.x * blockDim.x + threadIdx.x;
    if (e < EE) {
        int p = atomicAdd(&g_cur[dst[e]], 1);
        g_csrc[p] = src[e];
        g_ceid[p] = e;
    }
}

// ---------------- fused softmax + aggregation (+optional AT write) ----------
#define EXP_CAP 128
template <int D, int WRITE_AT>
__global__ void agg_fused(const float* __restrict__ C, float* __restrict__ out,
                          float* __restrict__ AT, int NCATP, int use_edge) {
    constexpr int DG = D / 4;
    __shared__ float s_exp[EXP_CAP][4];
    __shared__ float s_mx[4], s_inv[4];
    __shared__ float4 s_red[4 * DG];

    int n = blockIdx.x;
    int tid = threadIdx.x;
    int b = g_off[n];
    int deg = g_off[n + 1] - b;
    int colE = 5 * D;

    if (tid < 32) {
        int lane = tid, h = lane & 3;
        float ern = C[(size_t)n * NCATP + colE + 4 + h];
        int deg4 = deg * 4;
        float mx = -1e30f;
        for (int t = lane; t < deg4; t += 32) {
            int p = b + (t >> 2);
            float e = C[(size_t)g_csrc[p] * NCATP + colE + h] + ern;
            if (use_edge) e += g_eedge[(size_t)g_ceid[p] * 4 + h];
            e = e > 0.f ? e : 0.2f * e;
            mx = fmaxf(mx, e);
        }
        mx = fmaxf(mx, __shfl_xor_sync(0xffffffffu, mx, 4));
        mx = fmaxf(mx, __shfl_xor_sync(0xffffffffu, mx, 8));
        mx = fmaxf(mx, __shfl_xor_sync(0xffffffffu, mx, 16));
        float sum = 0.f;
        for (int t = lane; t < deg4; t += 32) {
            int p = b + (t >> 2);
            float e = C[(size_t)g_csrc[p] * NCATP + colE + h] + ern;
            if (use_edge) e += g_eedge[(size_t)g_ceid[p] * 4 + h];
            e = e > 0.f ? e : 0.2f * e;
            float ex = expf(e - mx);
            if ((t >> 2) < EXP_CAP) s_exp[t >> 2][h] = ex;
            sum += ex;
        }
        sum += __shfl_xor_sync(0xffffffffu, sum, 4);
        sum += __shfl_xor_sync(0xffffffffu, sum, 8);
        sum += __shfl_xor_sync(0xffffffffu, sum, 16);
        if (lane < 4) { s_mx[h] = mx; s_inv[h] = 1.f / (sum + 1e-9f); }
    }
    __syncthreads();

    int h = tid / DG, dg = tid % DG;
    float4 acc = make_float4(0.f, 0.f, 0.f, 0.f);
    const float* fbase = C + h * D + dg * 4;
    float mxh = s_mx[h];
    for (int q = 0; q < deg; q++) {
        int p = b + q;
        int s = g_csrc[p];
        float a;
        if (q < EXP_CAP) a = s_exp[q][h];
        else {
            float e = C[(size_t)s * NCATP + colE + h] + C[(size_t)n * NCATP + colE + 4 + h];
            if (use_edge) e += g_eedge[(size_t)g_ceid[p] * 4 + h];
            e = e > 0.f ? e : 0.2f * e;
            a = expf(e - mxh);
        }
        float4 f = *(const float4*)(fbase + (size_t)s * NCATP);
        acc.x = fmaf(a, f.x, acc.x);
        acc.y = fmaf(a, f.y, acc.y);
        acc.z = fmaf(a, f.z, acc.z);
        acc.w = fmaf(a, f.w, acc.w);
    }
    float sc = s_inv[h] * 0.25f;
    acc.x *= sc; acc.y *= sc; acc.z *= sc; acc.w *= sc;

    s_red[tid] = acc;
    __syncthreads();
    if (tid < DG) {
        float4 r0 = s_red[tid], r1 = s_red[DG + tid], r2 = s_red[2 * DG + tid], r3 = s_red[3 * DG + tid];
        float4 rr = *(const float4*)(C + (size_t)n * NCATP + 4 * D + tid * 4);
        float4 o;
        o.x = fmaxf(r0.x + r1.x + r2.x + r3.x + rr.x, 0.f);
        o.y = fmaxf(r0.y + r1.y + r2.y + r3.y + rr.y, 0.f);
        o.z = fmaxf(r0.z + r1.z + r2.z + r3.z + rr.z, 0.f);
        o.w = fmaxf(r0.w + r1.w + r2.w + r3.w + rr.w, 0.f);
        *(float4*)(out + (size_t)n * D + tid * 4) = o;
        if (WRITE_AT) {
            AT[(size_t)(tid * 4 + 0) * MPAD + n] = o.x;
            AT[(size_t)(tid * 4 + 1) * MPAD + n] = o.y;
            AT[(size_t)(tid * 4 + 2) * MPAD + n] = o.z;
            AT[(size_t)(tid * 4 + 3) * MPAD + n] = o.w;
        }
    }
}

// ---------------- host orchestration ----------------
extern "C" void kernel_launch(void* const* d_in, const int* in_sizes, int n_in,
                              void* d_out, int out_size) {
    const float* x0  = (const float*)d_in[0];
    const float* ef  = (const float*)d_in[1];
    const int*   src = (const int*)d_in[2];
    const int*   dst = (const int*)d_in[3];
    const float* W[4]   = {(const float*)d_in[4],  (const float*)d_in[10],
                           (const float*)d_in[14], (const float*)d_in[18]};
    const float* We1    = (const float*)d_in[5];
    const float* al[4]  = {(const float*)d_in[6],  (const float*)d_in[11],
                           (const float*)d_in[15], (const float*)d_in[19]};
    const float* ar[4]  = {(const float*)d_in[7],  (const float*)d_in[12],
                           (const float*)d_in[16], (const float*)d_in[20]};
    const float* ae1    = (const float*)d_in[8];
    const float* res[4] = {(const float*)d_in[9],  (const float*)d_in[13],
                           (const float*)d_in[17], (const float*)d_in[21]};

    float *p_C, *p_Bcat, *p_hA, *p_hB, *p_AT;
    cudaGetSymbolAddress((void**)&p_C,    g_C);
    cudaGetSymbolAddress((void**)&p_Bcat, g_Bcat);
    cudaGetSymbolAddress((void**)&p_hA,   g_hA);
    cudaGetSymbolAddress((void**)&p_hB,   g_hB);
    cudaGetSymbolAddress((void**)&p_AT,   g_AT);

    dim3 tgrid(MPAD / 32, 4), tblk(32, 8);

    float* houts[4] = {p_hA, p_hB, p_hA, (float*)d_out};
    int Dl[4]    = {128, 128, 128, 256};
    int NCATP_[4] = {768, 768, 768, 1408};

    for (int L = 0; L < 4; L++) {
        int D = Dl[L];
        int NCATP = NCATP_[L];
        if (L == 0) transpose_kernel<<<tgrid, tblk>>>(x0, p_AT, NN);
        bcat_kernel<<<(128 * NCATP + 255) / 256, 256>>>(W[L], res[L], p_Bcat, D, NCATP);
        contract_kernel<<<2, 256>>>(W[L], al[L], ar[L], p_Bcat, D, NCATP);
        dim3 gg((MPAD + 127) / 128, NCATP / 128);
        sgemm_tc<<<gg, 256>>>(p_AT, p_Bcat, p_C, NN, NCATP);   // 4th launch on L0 → ncu
        if (L == 0) {
            contract_we<<<1, 256>>>(We1, ae1);
            eedge_kernel<<<EE / 64, 256>>>(ef);
            zero_cur<<<(NN + 255) / 256, 256>>>();
            count_kernel<<<(EE + 255) / 256, 256>>>(dst);
            scan_kernel<<<1, 1024>>>();
            scatter_kernel<<<(EE + 255) / 256, 256>>>(src, dst);
        }
        if (D == 128) {
            if (L < 3) agg_fused<128, 1><<<NN, 128>>>(p_C, houts[L], p_AT, NCATP, L == 0 ? 1 : 0);
            else       agg_fused<128, 0><<<NN, 128>>>(p_C, houts[L], p_AT, NCATP, 0);
        } else {
            agg_fused<256, 0><<<NN, 256>>>(p_C, houts[L], p_AT, NCATP, 0);
        }
    }
}

// round 6
// speedup vs baseline: 1.3532x; 1.3532x over previous
#include <cuda_runtime.h>
#include <cuda_bf16.h>
#include <math.h>
#include <stdint.h>

#define NN 10000
#define EE 160000
#define HH 4
#define MPAD 10112   // 79 * 128

// ---------------- static scratch ----------------
__device__ float g_C [NN * 1408];              // [N, NCATP] (feat|res|el|er|pad)
__device__ __nv_bfloat16 g_A2[MPAD * 384];     // [M, 384] = [hi | hi | lo]
__device__ __nv_bfloat16 g_B2[384 * 1408];     // [384, NCATP] = [hi ; lo ; hi]
__device__ float g_hA  [NN * 128];
__device__ float g_hB  [NN * 128];
__device__ float g_eedge[EE * HH];
__device__ float g_inv [NN * HH];
__device__ float g_alpha[EE * HH];
__device__ int   g_off [NN + 1];
__device__ int   g_cur [NN];
__device__ int   g_csrc[EE];
__device__ int   g_ceid[EE];
__device__ float g_wev [64 * HH];

__device__ __forceinline__ uint32_t smem_u32(const void* p) {
    return (uint32_t)__cvta_generic_to_shared(p);
}
__device__ __forceinline__ void cpa16(uint32_t s, const void* g) {
    asm volatile("cp.async.cg.shared.global [%0], [%1], 16;" :: "r"(s), "l"(g));
}

// ---------------- fp32 -> (hi, lo) bf16 ----------------
__device__ __forceinline__ void bf16split(float v, __nv_bfloat16& hi, __nv_bfloat16& lo) {
    hi = __float2bfloat16(v);
    lo = __float2bfloat16(v - __bfloat162float(hi));
}

// ---------------- layer-0 input conversion ----------------
__global__ void conv_x(const float* __restrict__ x) {
    int i = blockIdx.x * blockDim.x + threadIdx.x;
    if (i >= NN * 128) return;
    int row = i >> 7, col = i & 127;
    __nv_bfloat16 hi, lo;
    bf16split(x[i], hi, lo);
    size_t base = (size_t)row * 384 + col;
    g_A2[base]       = hi;
    g_A2[base + 128] = hi;
    g_A2[base + 256] = lo;
}

// ---------------- B2 = [W | res | (el/er via contract) | 0], bf16 split -----
__global__ void bcat2_kernel(const float* __restrict__ W, const float* __restrict__ res,
                             int D, int NCATP) {
    int t = blockIdx.x * blockDim.x + threadIdx.x;
    if (t >= 128 * NCATP) return;
    int i = t / NCATP, c = t - i * NCATP;
    float v = 0.f;
    if (c < 4 * D)      v = W[(size_t)i * 4 * D + c];
    else if (c < 5 * D) v = res[(size_t)i * D + (c - 4 * D)];
    __nv_bfloat16 hi, lo;
    bf16split(v, hi, lo);
    g_B2[(size_t)i * NCATP + c]           = hi;
    g_B2[(size_t)(i + 128) * NCATP + c]   = lo;
    g_B2[(size_t)(i + 256) * NCATP + c]   = hi;
}

__global__ void contract_kernel(const float* __restrict__ W,
                                const float* __restrict__ vl, const float* __restrict__ vr,
                                int D, int NCATP) {
    int t = blockIdx.x * blockDim.x + threadIdx.x;
    if (t >= 128 * HH) return;
    int i = t >> 2, h = t & 3;
    const float* wr = W + (size_t)(i * HH + h) * D;
    const float* al = vl + h * D;
    const float* ar = vr + h * D;
    float sl = 0.f, sr = 0.f;
    for (int d = 0; d < D; d++) {
        float w = wr[d];
        sl = fmaf(w, al[d], sl);
        sr = fmaf(w, ar[d], sr);
    }
    __nv_bfloat16 hi, lo;
    int cL = 5 * D + h, cR = 5 * D + 4 + h;
    bf16split(sl, hi, lo);
    g_B2[(size_t)i * NCATP + cL] = hi;
    g_B2[(size_t)(i + 128) * NCATP + cL] = lo;
    g_B2[(size_t)(i + 256) * NCATP + cL] = hi;
    bf16split(sr, hi, lo);
    g_B2[(size_t)i * NCATP + cR] = hi;
    g_B2[(size_t)(i + 128) * NCATP + cR] = lo;
    g_B2[(size_t)(i + 256) * NCATP + cR] = hi;
}

__global__ void contract_we(const float* __restrict__ We, const float* __restrict__ ae) {
    int t = blockIdx.x * blockDim.x + threadIdx.x;
    if (t >= 64 * HH) return;
    int i = t >> 2, h = t & 3;
    const float* wr = We + (size_t)(i * HH + h) * 128;
    const float* a  = ae + h * 128;
    float s = 0.f;
    for (int d = 0; d < 128; d++) s = fmaf(wr[d], a[d], s);
    g_wev[t] = s;
}

// ---------------- bf16 HMMA GEMM: C[M,Nc] = A2[M,384] @ B2[384,Nc] ----------
// BM=128, BN=128, BK=32, 256 thr (8 warps 2x4), warp tile 64x32, m16n8k16.
__global__ void __launch_bounds__(256) mma_gemm(
        const __nv_bfloat16* __restrict__ A2, const __nv_bfloat16* __restrict__ B2,
        float* __restrict__ C, int Nc) {
    __shared__ __nv_bfloat16 As[2][128][40];   // 32 cols + 8 pad
    __shared__ __nv_bfloat16 Bs[2][32][136];   // 128 cols + 8 pad
    int tid = threadIdx.x, wid = tid >> 5, lane = tid & 31;
    int wm = (wid & 1) * 64;
    int wn = (wid >> 1) * 32;
    int rowBase = blockIdx.x * 128;
    int colBase = blockIdx.y * 128;

    float c[4][4][4];
#pragma unroll
    for (int i = 0; i < 4; i++)
#pragma unroll
        for (int j = 0; j < 4; j++)
#pragma unroll
            for (int r = 0; r < 4; r++) c[i][j][r] = 0.f;

    // chunk mappings (16B = 8 bf16 per chunk; 2 chunks/thread for each of A, B)
    int ra0 = tid >> 2,          ca0 = (tid & 3) * 8;
    int ra1 = (tid + 256) >> 2,  ca1 = ((tid + 256) & 3) * 8;
    int rb0 = tid >> 4,          cb0 = (tid & 15) * 8;
    int rb1 = (tid + 256) >> 4,  cb1 = ((tid + 256) & 15) * 8;

#define LOAD_STAGE(kb, st) do { \
        int k0 = (kb) * 32; \
        cpa16(smem_u32(&As[st][ra0][ca0]), A2 + (size_t)(rowBase + ra0) * 384 + k0 + ca0); \
        cpa16(smem_u32(&As[st][ra1][ca1]), A2 + (size_t)(rowBase + ra1) * 384 + k0 + ca1); \
        cpa16(smem_u32(&Bs[st][rb0][cb0]), B2 + (size_t)(k0 + rb0) * Nc + colBase + cb0); \
        cpa16(smem_u32(&Bs[st][rb1][cb1]), B2 + (size_t)(k0 + rb1) * Nc + colBase + cb1); \
        asm volatile("cp.async.commit_group;" ::: "memory"); \
    } while (0)

    LOAD_STAGE(0, 0);

    for (int kb = 0; kb < 12; kb++) {
        int cur = kb & 1;
        asm volatile("cp.async.wait_group 0;" ::: "memory");
        __syncthreads();
        if (kb < 11) LOAD_STAGE(kb + 1, cur ^ 1);

#pragma unroll
        for (int kk = 0; kk < 32; kk += 16) {
            uint32_t a[4][4];
#pragma unroll
            for (int i = 0; i < 4; i++) {
                uint32_t ad = smem_u32(&As[cur][wm + i * 16 + (lane & 15)][kk + (lane >> 4) * 8]);
                asm volatile("ldmatrix.sync.aligned.m8n8.x4.shared.b16 {%0,%1,%2,%3}, [%4];"
                    : "=r"(a[i][0]), "=r"(a[i][1]), "=r"(a[i][2]), "=r"(a[i][3]) : "r"(ad));
            }
            uint32_t b[4][2];
#pragma unroll
            for (int j2 = 0; j2 < 2; j2++) {
                uint32_t bd = smem_u32(&Bs[cur][kk + (lane & 15)][wn + j2 * 16 + (lane >> 4) * 8]);
                asm volatile("ldmatrix.sync.aligned.m8n8.x4.trans.shared.b16 {%0,%1,%2,%3}, [%4];"
                    : "=r"(b[j2 * 2][0]), "=r"(b[j2 * 2][1]), "=r"(b[j2 * 2 + 1][0]), "=r"(b[j2 * 2 + 1][1]) : "r"(bd));
            }
#pragma unroll
            for (int i = 0; i < 4; i++)
#pragma unroll
                for (int j = 0; j < 4; j++)
                    asm volatile("mma.sync.aligned.m16n8k16.row.col.f32.bf16.bf16.f32 "
                        "{%0,%1,%2,%3}, {%4,%5,%6,%7}, {%8,%9}, {%0,%1,%2,%3};"
                        : "+f"(c[i][j][0]), "+f"(c[i][j][1]), "+f"(c[i][j][2]), "+f"(c[i][j][3])
                        : "r"(a[i][0]), "r"(a[i][1]), "r"(a[i][2]), "r"(a[i][3]),
                          "r"(b[j][0]), "r"(b[j][1]));
        }
    }
#undef LOAD_STAGE

#pragma unroll
    for (int i = 0; i < 4; i++) {
        int row = rowBase + wm + i * 16 + (lane >> 2);
#pragma unroll
        for (int j = 0; j < 4; j++) {
            int col = colBase + wn + j * 8 + (lane & 3) * 2;
            if (row < NN)
                *(float2*)(C + (size_t)row * Nc + col) = make_float2(c[i][j][0], c[i][j][1]);
            if (row + 8 < NN)
                *(float2*)(C + (size_t)(row + 8) * Nc + col) = make_float2(c[i][j][2], c[i][j][3]);
        }
    }
}

// ---------------- edge logit term (layer 1 only) ----------------
__global__ void __launch_bounds__(256) eedge_kernel(const float* __restrict__ ef) {
    __shared__ float sf[64][68];
    __shared__ float sw[64 * HH];
    int tid = threadIdx.x;
    int e0 = blockIdx.x * 64;
    sw[tid] = g_wev[tid];
#pragma unroll
    for (int j = 0; j < 4; j++) {
        int idx = tid + j * 256;
        int e = idx >> 4, q = idx & 15;
        float4 v = *(const float4*)(ef + (size_t)(e0 + e) * 64 + q * 4);
        *(float4*)&sf[e][q * 4] = v;
    }
    __syncthreads();
    int e = tid >> 2, h = tid & 3;
    float acc = 0.f;
#pragma unroll
    for (int d = 0; d < 64; d++)
        acc = fmaf(sf[e][d], sw[d * 4 + h], acc);
    g_eedge[(size_t)(e0 + e) * 4 + h] = acc;
}

// ---------------- CSR build ----------------
__global__ void zero_cur() {
    int i = blockIdx.x * blockDim.x + threadIdx.x;
    if (i < NN) g_cur[i] = 0;
}
__global__ void count_kernel(const int* __restrict__ dst) {
    int e = blockIdx.x * blockDim.x + threadIdx.x;
    if (e < EE) atomicAdd(&g_cur[dst[e]], 1);
}
__global__ void scan_kernel() {
    __shared__ int sh[1024];
    int t = threadIdx.x;
    int vals[10];
    int base = t * 10;
    int s = 0;
#pragma unroll
    for (int j = 0; j < 10; j++) {
        int idx = base + j;
        int v = (idx < NN) ? g_cur[idx] : 0;
        vals[j] = s;
        s += v;
    }
    sh[t] = s;
    __syncthreads();
    for (int off = 1; off < 1024; off <<= 1) {
        int v = (t >= off) ? sh[t - off] : 0;
        __syncthreads();
        sh[t] += v;
        __syncthreads();
    }
    int excl = (t > 0) ? sh[t - 1] : 0;
#pragma unroll
    for (int j = 0; j < 10; j++) {
        int idx = base + j;
        if (idx < NN) {
            int o = excl + vals[j];
            g_off[idx] = o;
            g_cur[idx] = o;
        }
    }
    if (t == 1023) g_off[NN] = sh[1023];
}
__global__ void scatter_kernel(const int* __restrict__ src, const int* __restrict__ dst) {
    int e = blockIdx.x * blockDim.x + threadIdx.x;
    if (e < EE) {
        int p = atomicAdd(&g_cur[dst[e]], 1);
        g_csrc[p] = src[e];
        g_ceid[p] = e;
    }
}

// ---------------- edge softmax ----------------
__global__ void alpha_kernel(const float* __restrict__ C, int D, int NCATP, int use_edge) {
    int warp = (blockIdx.x * blockDim.x + threadIdx.x) >> 5;
    int lane = threadIdx.x & 31;
    if (warp >= NN) return;
    int n = warp;
    int b = g_off[n];
    int deg4 = (g_off[n + 1] - b) * 4;
    int h = lane & 3;
    int colE = 5 * D;
    float ern = C[(size_t)n * NCATP + colE + 4 + h];

    float mx = -1e30f;
    for (int t = lane; t < deg4; t += 32) {
        int p = b + (t >> 2);
        float e = C[(size_t)g_csrc[p] * NCATP + colE + h] + ern;
        if (use_edge) e += g_eedge[(size_t)g_ceid[p] * 4 + h];
        e = e > 0.f ? e : 0.2f * e;
        mx = fmaxf(mx, e);
    }
    mx = fmaxf(mx, __shfl_xor_sync(0xffffffffu, mx, 4));
    mx = fmaxf(mx, __shfl_xor_sync(0xffffffffu, mx, 8));
    mx = fmaxf(mx, __shfl_xor_sync(0xffffffffu, mx, 16));

    float sum = 0.f;
    for (int t = lane; t < deg4; t += 32) {
        int p = b + (t >> 2);
        float e = C[(size_t)g_csrc[p] * NCATP + colE + h] + ern;
        if (use_edge) e += g_eedge[(size_t)g_ceid[p] * 4 + h];
        e = e > 0.f ? e : 0.2f * e;
        float ex = expf(e - mx);
        g_alpha[(size_t)p * 4 + h] = ex;
        sum += ex;
    }
    sum += __shfl_xor_sync(0xffffffffu, sum, 4);
    sum += __shfl_xor_sync(0xffffffffu, sum, 8);
    sum += __shfl_xor_sync(0xffffffffu, sum, 16);
    if (lane < 4) g_inv[n * 4 + h] = 1.f / (sum + 1e-9f);
}

// ---------------- aggregation (+bf16 A2 write for next layer) ----------------
template <int D, int WRITE_BF16>
__global__ void agg_kernel(const float* __restrict__ C, float* __restrict__ out, int NCATP) {
    constexpr int DG = D / 4;
    int n = blockIdx.x;
    int tid = threadIdx.x;
    int h = tid / DG;
    int dg = tid % DG;
    int b = g_off[n], e = g_off[n + 1];
    float4 acc = make_float4(0.f, 0.f, 0.f, 0.f);
    const float* fbase = C + h * D + dg * 4;
    for (int p = b; p < e; ++p) {
        int s = g_csrc[p];
        float a = g_alpha[(size_t)p * 4 + h];
        float4 f = *(const float4*)(fbase + (size_t)s * NCATP);
        acc.x = fmaf(a, f.x, acc.x);
        acc.y = fmaf(a, f.y, acc.y);
        acc.z = fmaf(a, f.z, acc.z);
        acc.w = fmaf(a, f.w, acc.w);
    }
    float sc = g_inv[n * 4 + h] * 0.25f;
    acc.x *= sc; acc.y *= sc; acc.z *= sc; acc.w *= sc;

    __shared__ float4 sh[4 * DG];
    sh[tid] = acc;
    __syncthreads();
    if (tid < DG) {
        float4 r0 = sh[tid], r1 = sh[DG + tid], r2 = sh[2 * DG + tid], r3 = sh[3 * DG + tid];
        float4 rr = *(const float4*)(C + (size_t)n * NCATP + 4 * D + tid * 4);
        float4 o;
        o.x = fmaxf(r0.x + r1.x + r2.x + r3.x + rr.x, 0.f);
        o.y = fmaxf(r0.y + r1.y + r2.y + r3.y + rr.y, 0.f);
        o.z = fmaxf(r0.z + r1.z + r2.z + r3.z + rr.z, 0.f);
        o.w = fmaxf(r0.w + r1.w + r2.w + r3.w + rr.w, 0.f);
        *(float4*)(out + (size_t)n * D + tid * 4) = o;
        if (WRITE_BF16) {
            size_t base = (size_t)n * 384 + tid * 4;
            float vv[4] = {o.x, o.y, o.z, o.w};
#pragma unroll
            for (int j = 0; j < 4; j++) {
                __nv_bfloat16 hi, lo;
                bf16split(vv[j], hi, lo);
                g_A2[base + j]       = hi;
                g_A2[base + 128 + j] = hi;
                g_A2[base + 256 + j] = lo;
            }
        }
    }
}

// ---------------- host orchestration ----------------
extern "C" void kernel_launch(void* const* d_in, const int* in_sizes, int n_in,
                              void* d_out, int out_size) {
    const float* x0  = (const float*)d_in[0];
    const float* ef  = (const float*)d_in[1];
    const int*   src = (const int*)d_in[2];
    const int*   dst = (const int*)d_in[3];
    const float* W[4]   = {(const float*)d_in[4],  (const float*)d_in[10],
                           (const float*)d_in[14], (const float*)d_in[18]};
    const float* We1    = (const float*)d_in[5];
    const float* al[4]  = {(const float*)d_in[6],  (const float*)d_in[11],
                           (const float*)d_in[15], (const float*)d_in[19]};
    const float* ar[4]  = {(const float*)d_in[7],  (const float*)d_in[12],
                           (const float*)d_in[16], (const float*)d_in[20]};
    const float* ae1    = (const float*)d_in[8];
    const float* res[4] = {(const float*)d_in[9],  (const float*)d_in[13],
                           (const float*)d_in[17], (const float*)d_in[21]};

    float *p_C, *p_hA, *p_hB;
    __nv_bfloat16 *p_A2, *p_B2;
    cudaGetSymbolAddress((void**)&p_C,  g_C);
    cudaGetSymbolAddress((void**)&p_hA, g_hA);
    cudaGetSymbolAddress((void**)&p_hB, g_hB);
    cudaGetSymbolAddress((void**)&p_A2, g_A2);
    cudaGetSymbolAddress((void**)&p_B2, g_B2);

    float* houts[4] = {p_hA, p_hB, p_hA, (float*)d_out};
    int Dl[4]     = {128, 128, 128, 256};
    int NCATP_[4] = {768, 768, 768, 1408};

    for (int L = 0; L < 4; L++) {
        int D = Dl[L];
        int NCATP = NCATP_[L];
        if (L == 0) conv_x<<<(NN * 128 + 255) / 256, 256>>>(x0);                 // 1
        bcat2_kernel<<<(128 * NCATP + 255) / 256, 256>>>(W[L], res[L], D, NCATP); // 2
        contract_kernel<<<2, 256>>>(W[L], al[L], ar[L], D, NCATP);               // 3
        dim3 gg(MPAD / 128, NCATP / 128);
        mma_gemm<<<gg, 256>>>(p_A2, p_B2, p_C, NCATP);                           // 4 -> ncu
        if (L == 0) {
            contract_we<<<1, 256>>>(We1, ae1);
            eedge_kernel<<<EE / 64, 256>>>(ef);
            zero_cur<<<(NN + 255) / 256, 256>>>();
            count_kernel<<<(EE + 255) / 256, 256>>>(dst);
            scan_kernel<<<1, 1024>>>();
            scatter_kernel<<<(EE + 255) / 256, 256>>>(src, dst);
        }
        alpha_kernel<<<(NN * 32 + 255) / 256, 256>>>(p_C, D, NCATP, L == 0 ? 1 : 0);
        if (D == 128) {
            if (L < 3) agg_kernel<128, 1><<<NN, 128>>>(p_C, houts[L], NCATP);
            else       agg_kernel<128, 0><<<NN, 128>>>(p_C, houts[L], NCATP);
        } else {
            agg_kernel<256, 0><<<NN, 256>>>(p_C, houts[L], NCATP);
        }
    }
}